// round 1
// baseline (speedup 1.0000x reference)
#include <cuda_runtime.h>

#define BETA   0.95f
#define THR    1.0f
#define NSTEP  25
#define NIN    9
#define NHID   100
#define NOUT   2

__global__ __launch_bounds__(64) void snn_kernel(
    const float* __restrict__ x,
    const float* __restrict__ W1,
    const float* __restrict__ b1,
    const float* __restrict__ W2,
    const float* __restrict__ b2,
    float* __restrict__ out,
    int batch)
{
    __shared__ float sW1[NHID * NIN];
    __shared__ float sb1[NHID];
    __shared__ float sW2[NOUT * NHID];
    __shared__ float sb2[NOUT];

    for (int i = threadIdx.x; i < NHID * NIN; i += blockDim.x) sW1[i] = W1[i];
    for (int i = threadIdx.x; i < NHID;       i += blockDim.x) sb1[i] = b1[i];
    for (int i = threadIdx.x; i < NOUT*NHID;  i += blockDim.x) sW2[i] = W2[i];
    if (threadIdx.x < NOUT) sb2[threadIdx.x] = b2[threadIdx.x];
    __syncthreads();

    int b = blockIdx.x * blockDim.x + threadIdx.x;
    if (b >= batch) return;

    // x row for this batch element
    float xv[NIN];
#pragma unroll
    for (int i = 0; i < NIN; i++) xv[i] = __ldg(&x[(size_t)b * NIN + i]);

    // per-timestep layer-2 input accumulators (registers, fully unrolled)
    float acc0[NSTEP], acc1[NSTEP];
#pragma unroll
    for (int t = 0; t < NSTEP; t++) { acc0[t] = 0.0f; acc1[t] = 0.0f; }

    // Loop over hidden neurons, 2 at a time for ILP across the serial
    // membrane-recurrence chain.
    for (int h = 0; h < NHID; h += 2) {
        float c0 = sb1[h];
        float c1 = sb1[h + 1];
#pragma unroll
        for (int i = 0; i < NIN; i++) {
            c0 = fmaf(xv[i], sW1[h * NIN + i],       c0);
            c1 = fmaf(xv[i], sW1[(h + 1) * NIN + i], c1);
        }
        const float w00 = sW2[h],     w01 = sW2[NHID + h];
        const float w10 = sW2[h + 1], w11 = sW2[NHID + h + 1];

        float m0 = 0.0f, m1 = 0.0f;   // membrane potentials
        float r0 = 0.0f, r1 = 0.0f;   // reset (== spike from previous step, THR=1)
#pragma unroll
        for (int t = 0; t < NSTEP; t++) {
            // mem = beta*mem + cur - reset(prev mem)   (reset_mechanism='subtract')
            m0 = fmaf(BETA, m0, c0) - r0;
            m1 = fmaf(BETA, m1, c1) - r1;
            // spike from the NEW membrane (heaviside, strict >)
            r0 = (m0 > THR) ? 1.0f : 0.0f;
            r1 = (m1 > THR) ? 1.0f : 0.0f;
            // cur2[t] += spk * W2 columns (r in {0,1}, THR==1 so r doubles as spike)
            acc0[t] = fmaf(r0, w00, acc0[t]);
            acc1[t] = fmaf(r0, w01, acc1[t]);
            acc0[t] = fmaf(r1, w10, acc0[t]);
            acc1[t] = fmaf(r1, w11, acc1[t]);
        }
    }

    // Layer-2 LIF recurrence + output record (mem2 after each update)
    const float bb0 = sb2[0], bb1 = sb2[1];
    float m20 = 0.0f, m21 = 0.0f;
    float2* outv = (float2*)out;
#pragma unroll
    for (int t = 0; t < NSTEP; t++) {
        float rr0 = (m20 > THR) ? 1.0f : 0.0f;   // reset from PREVIOUS mem2
        float rr1 = (m21 > THR) ? 1.0f : 0.0f;
        m20 = fmaf(BETA, m20, acc0[t] + bb0) - rr0;
        m21 = fmaf(BETA, m21, acc1[t] + bb1) - rr1;
        outv[(size_t)t * batch + b] = make_float2(m20, m21);
    }
}

extern "C" void kernel_launch(void* const* d_in, const int* in_sizes, int n_in,
                              void* d_out, int out_size)
{
    const float* x  = (const float*)d_in[0];
    const float* W1 = (const float*)d_in[1];
    const float* b1 = (const float*)d_in[2];
    const float* W2 = (const float*)d_in[3];
    const float* b2 = (const float*)d_in[4];
    float* out = (float*)d_out;

    int batch = in_sizes[0] / NIN;
    const int threads = 64;
    int blocks = (batch + threads - 1) / threads;
    snn_kernel<<<blocks, threads>>>(x, W1, b1, W2, b2, out, batch);
}